// round 15
// baseline (speedup 1.0000x reference)
#include <cuda_runtime.h>
#include <cuda_fp16.h>
#include <cstdint>
#include <math.h>

#define SDIM 2048
#define HDIM 2048
#define ANUM 16
#define NB1  256      // K1: 128 typeA + 128 typeB (single wave at 2 blocks/SM)
#define NA1  128
#define NB_2 256      // K2 blocks
#define NB_3 256      // K3 blocks
#define CH1  16       // K1 chunks per row (2048 / 128)
#define CC1  128      // halfs per chunk per stream (256 B)
#define CH   8        // K2/K3 chunks per row (2048 / 256)
#define CC   256      // halfs per chunk per row
#define NSTG 3

// Persistent scratch
__device__ __align__(16) float g_h0[2][HDIM];
__device__ __align__(16) float g_h1[2][HDIM];
__device__ __align__(16) float g_c[2][HDIM];
__device__ __align__(16) float g_pre1[4 * HDIM];
__device__ __align__(16) float g_logits[SDIM];
__device__ __align__(16) float g_partial[NB_3];
__device__ __align__(16) __half g_wih16[2 * 4 * HDIM * HDIM];
__device__ __align__(16) __half g_whh16[2 * 4 * HDIM * HDIM];
__device__ __align__(16) __half g_wout16[SDIM * HDIM];

__device__ __forceinline__ float sigmoidf_(float x) {
    return 1.0f / (1.0f + __expf(-x));
}

__device__ __forceinline__ void cp16(uint32_t dst, const void* src) {
    asm volatile("cp.async.cg.shared.global [%0], [%1], 16;"
                 :: "r"(dst), "l"(src) : "memory");
}
__device__ __forceinline__ void cp8(uint32_t dst, const void* src) {
    asm volatile("cp.async.ca.shared.global [%0], [%1], 8;"
                 :: "r"(dst), "l"(src) : "memory");
}
#define CP_COMMIT() asm volatile("cp.async.commit_group;" ::: "memory")
#define CP_WAIT1()  asm volatile("cp.async.wait_group 1;"  ::: "memory")

// 8 half-weights (uint4) dot 8 floats, two accumulators (K2/K3).
__device__ __forceinline__ void dot8(uint4 w, float4 lo, float4 hi,
                                     float& p, float& q) {
    const __half2* hp = reinterpret_cast<const __half2*>(&w);
    float2 f0 = __half22float2(hp[0]);
    float2 f1 = __half22float2(hp[1]);
    float2 f2 = __half22float2(hp[2]);
    float2 f3 = __half22float2(hp[3]);
    p = fmaf(f0.x, lo.x, p); q = fmaf(f0.y, lo.y, q);
    p = fmaf(f1.x, lo.z, p); q = fmaf(f1.y, lo.w, q);
    p = fmaf(f2.x, hi.x, p); q = fmaf(f2.y, hi.y, q);
    p = fmaf(f3.x, hi.z, p); q = fmaf(f3.y, hi.w, q);
}

// 4 half-weights (uint2) dot 4 floats, two accumulators (K1).
__device__ __forceinline__ void dot4h(uint2 w, float4 a, float& p, float& q) {
    __half2 h0 = *reinterpret_cast<__half2*>(&w.x);
    __half2 h1 = *reinterpret_cast<__half2*>(&w.y);
    float2 f0 = __half22float2(h0);
    float2 f1 = __half22float2(h1);
    p = fmaf(f0.x, a.x, p); q = fmaf(f0.y, a.y, q);
    p = fmaf(f1.x, a.z, p); q = fmaf(f1.y, a.w, q);
}

// ===========================================================================
// K1 (single wave): 256 blocks x 512 thr, 4 flat rows per warp.
// typeA (bid<128): 16 units/block, warp = (gate, 4 consecutive units),
//                  streams Wih0 + Whh0 rows (8 x 256B chunks).
// typeB (bid>=128): 64 Whh1 rows/block, 4 rows/warp (4 streams).
// Tile/warp: 3 stages x 2048B (8 segs x 256B) = 6 KB. Act 16 KB. Total 112 KB.
// ===========================================================================
template<int FIRST>
__global__ void __launch_bounds__(512, 2) step_k1(
    const __half* __restrict__ Wih0, const __half* __restrict__ Whh0,
    const __half* __restrict__ Whh1,
    const float* __restrict__ bih0, const float* __restrict__ bhh0,
    const float* __restrict__ bih1, const float* __restrict__ bhh1,
    const float* __restrict__ xin,
    const float* __restrict__ logits, const float* __restrict__ partials,
    float* __restrict__ out_prev,
    const float* __restrict__ h0_in, float* __restrict__ h0_out,
    const float* __restrict__ h1_in,
    float* __restrict__ c0, float* __restrict__ pre1)
{
    extern __shared__ __align__(16) char smem[];
    float4* sIn0 = (float4*)smem;
    float4* sIn1 = sIn0 + 256;
    float4* sH0  = sIn1 + 256;
    float4* sH1  = sH0 + 256;
    __half* tiles = (__half*)(smem + 16384);
    __shared__ float s_g[64];
    __shared__ float s_inv;

    const int t = threadIdx.x, warp = t >> 5, lane = t & 31;
    const bool typeA = (blockIdx.x < NA1);
    const uint32_t smemU = (uint32_t)__cvta_generic_to_shared(smem);
    const uint32_t tileU = smemU + 16384 + warp * 6144 + lane * 8;
    const __half* tileh  = tiles + warp * 3072;

    int row0;
    const __half *rA, *rB;
    if (typeA) {
        const int gate = warp & 3, ug = warp >> 2;
        row0 = gate * HDIM + blockIdx.x * 16 + ug * 4;
        rA = Wih0 + (size_t)row0 * HDIM;
        rB = Whh0 + (size_t)row0 * HDIM;
    } else {
        row0 = (blockIdx.x - NA1) * 64 + warp * 4;
        rA = Whh1 + (size_t)row0 * HDIM;
        rB = nullptr;
    }

    // prologue: chunks 0..NSTG-2
    if (typeA) {
        #pragma unroll
        for (int s = 0; s < NSTG - 1; s++) {
            const uint32_t d = tileU + s * 2048;
            #pragma unroll
            for (int r = 0; r < 4; r++) {
                cp8(d + r * 256,        rA + (size_t)r * HDIM + s * CC1 + lane * 4);
                cp8(d + 1024 + r * 256, rB + (size_t)r * HDIM + s * CC1 + lane * 4);
            }
            CP_COMMIT();
        }
    } else {
        #pragma unroll
        for (int s = 0; s < NSTG - 1; s++) {
            const uint32_t d = tileU + s * 2048;
            #pragma unroll
            for (int r = 0; r < 4; r++)
                cp8(d + r * 256, rA + (size_t)r * HDIM + s * CC1 + lane * 4);
            CP_COMMIT();
        }
    }

    // activation staging (overlaps cp.async latency)
    if (typeA) {
        if (!FIRST) {
            if (warp == 0) {
                float s = 0.0f;
                #pragma unroll
                for (int j = 0; j < 8; j++) s += partials[lane + j * 32];
                #pragma unroll
                for (int o = 16; o > 0; o >>= 1)
                    s += __shfl_xor_sync(0xffffffffu, s, o);
                if (lane == 0) s_inv = 1.0f / s;
            }
            __syncthreads();
        }
        float4 v;
        if (FIRST) {
            v = ((const float4*)xin)[t];
        } else {
            float4 lg = ((const float4*)logits)[t];
            const float inv = s_inv;
            v.x = __expf(lg.x) * inv;
            v.y = __expf(lg.y) * inv;
            v.z = __expf(lg.z) * inv;
            v.w = __expf(lg.w) * inv;
            if (blockIdx.x == 0) ((float4*)out_prev)[t] = v;
        }
        ((t & 1) ? sIn1 : sIn0)[t >> 1] = v;
        float4 hv = ((const float4*)h0_in)[t];
        ((t & 1) ? sH1 : sH0)[t >> 1] = hv;
    } else {
        float4 hv = ((const float4*)h1_in)[t];
        ((t & 1) ? sIn1 : sIn0)[t >> 1] = hv;
    }
    __syncthreads();

    // streaming loop: 16 chunks of 256B per stream
    float p0 = 0.f, q0 = 0.f, p1 = 0.f, q1 = 0.f;
    float p2 = 0.f, q2 = 0.f, p3 = 0.f, q3 = 0.f;
    const int f0idx = lane;            // f = c*32 + lane
    if (typeA) {
        #pragma unroll 4
        for (int c = 0; c < CH1; c++) {
            CP_WAIT1();
            const int st = c % NSTG;
            const int f = c * 32 + f0idx;
            const float4 a = ((f & 1) ? sIn1 : sIn0)[f >> 1];
            const float4 b = ((f & 1) ? sH1 : sH0)[f >> 1];
            const __half* tp = tileh + st * 1024;   // halfs
            uint2 wA0 = *(const uint2*)(tp +           lane * 4);
            uint2 wA1 = *(const uint2*)(tp + 128 +     lane * 4);
            uint2 wA2 = *(const uint2*)(tp + 256 +     lane * 4);
            uint2 wA3 = *(const uint2*)(tp + 384 +     lane * 4);
            uint2 wB0 = *(const uint2*)(tp + 512 +     lane * 4);
            uint2 wB1 = *(const uint2*)(tp + 512 + 128 + lane * 4);
            uint2 wB2 = *(const uint2*)(tp + 512 + 256 + lane * 4);
            uint2 wB3 = *(const uint2*)(tp + 512 + 384 + lane * 4);
            dot4h(wA0, a, p0, q0); dot4h(wB0, b, p0, q0);
            dot4h(wA1, a, p1, q1); dot4h(wB1, b, p1, q1);
            dot4h(wA2, a, p2, q2); dot4h(wB2, b, p2, q2);
            dot4h(wA3, a, p3, q3); dot4h(wB3, b, p3, q3);
            const int nc = c + NSTG - 1;
            if (nc < CH1) {
                const uint32_t d = tileU + (nc % NSTG) * 2048;
                #pragma unroll
                for (int r = 0; r < 4; r++) {
                    cp8(d + r * 256,        rA + (size_t)r * HDIM + nc * CC1 + lane * 4);
                    cp8(d + 1024 + r * 256, rB + (size_t)r * HDIM + nc * CC1 + lane * 4);
                }
            }
            CP_COMMIT();
        }
    } else {
        #pragma unroll 4
        for (int c = 0; c < CH1; c++) {
            CP_WAIT1();
            const int st = c % NSTG;
            const int f = c * 32 + f0idx;
            const float4 a = ((f & 1) ? sIn1 : sIn0)[f >> 1];
            const __half* tp = tileh + st * 1024;
            uint2 w0 = *(const uint2*)(tp +       lane * 4);
            uint2 w1 = *(const uint2*)(tp + 128 + lane * 4);
            uint2 w2 = *(const uint2*)(tp + 256 + lane * 4);
            uint2 w3 = *(const uint2*)(tp + 384 + lane * 4);
            dot4h(w0, a, p0, q0);
            dot4h(w1, a, p1, q1);
            dot4h(w2, a, p2, q2);
            dot4h(w3, a, p3, q3);
            const int nc = c + NSTG - 1;
            if (nc < CH1) {
                const uint32_t d = tileU + (nc % NSTG) * 2048;
                #pragma unroll
                for (int r = 0; r < 4; r++)
                    cp8(d + r * 256, rA + (size_t)r * HDIM + nc * CC1 + lane * 4);
            }
            CP_COMMIT();
        }
    }

    // reduce 4 rows + epilogue
    float v0 = p0 + q0, v1 = p1 + q1, v2 = p2 + q2, v3 = p3 + q3;
    #pragma unroll
    for (int o = 16; o > 0; o >>= 1) {
        v0 += __shfl_xor_sync(0xffffffffu, v0, o);
        v1 += __shfl_xor_sync(0xffffffffu, v1, o);
        v2 += __shfl_xor_sync(0xffffffffu, v2, o);
        v3 += __shfl_xor_sync(0xffffffffu, v3, o);
    }
    if (typeA) {
        if (lane == 0) {
            const int gate = warp & 3, ug = warp >> 2;
            const int base = gate * 16 + ug * 4;
            s_g[base]     = v0 + bih0[row0]     + bhh0[row0];
            s_g[base + 1] = v1 + bih0[row0 + 1] + bhh0[row0 + 1];
            s_g[base + 2] = v2 + bih0[row0 + 2] + bhh0[row0 + 2];
            s_g[base + 3] = v3 + bih0[row0 + 3] + bhh0[row0 + 3];
        }
        __syncthreads();
        if (t < 16) {
            const int u = blockIdx.x * 16 + t;
            float iv = sigmoidf_(s_g[t]);
            float fv = sigmoidf_(s_g[16 + t]);
            float gv = tanhf(s_g[32 + t]);
            float ov = sigmoidf_(s_g[48 + t]);
            float cn = fv * c0[u] + iv * gv;
            c0[u]     = cn;
            h0_out[u] = ov * tanhf(cn);
        }
    } else {
        if (lane == 0) {
            pre1[row0]     = v0 + bih1[row0]     + bhh1[row0];
            pre1[row0 + 1] = v1 + bih1[row0 + 1] + bhh1[row0 + 1];
            pre1[row0 + 2] = v2 + bih1[row0 + 2] + bhh1[row0 + 2];
            pre1[row0 + 3] = v3 + bih1[row0 + 3] + bhh1[row0 + 3];
        }
    }
}

// ===========================================================================
// K2 (R11 verbatim): layer-1 input half + pointwise. 256 blocks, 2 rows/warp.
// ===========================================================================
__global__ void __launch_bounds__(512, 2) step_k2(
    const __half* __restrict__ Wih1,
    const float* __restrict__ pre1,
    const float* __restrict__ h0_new,
    float* __restrict__ h1_out, float* __restrict__ c1)
{
    extern __shared__ __align__(16) char smem[];
    float4* sA0 = (float4*)smem;
    float4* sA1 = sA0 + 256;
    __half* tiles = (__half*)(smem + 8192);
    __shared__ float s_g[32];

    const int t = threadIdx.x, warp = t >> 5, lane = t & 31;
    const uint32_t smemU = (uint32_t)__cvta_generic_to_shared(smem);
    const uint32_t tileU = smemU + 8192 + warp * 3072 + lane * 16;
    const __half* tileh  = tiles + warp * 1536;

    const int i0 = 2 * warp;
    const int rg0 = (i0 >> 3) * HDIM + blockIdx.x * 8 + (i0 & 7);
    const __half* rA0 = Wih1 + (size_t)rg0 * HDIM;

    #pragma unroll
    for (int s = 0; s < NSTG - 1; s++) {
        const uint32_t d = tileU + s * 1024;
        cp16(d,       rA0 + s * CC + lane * 8);
        cp16(d + 512, rA0 + HDIM + s * CC + lane * 8);
        CP_COMMIT();
    }

    {
        float4 hv = ((const float4*)h0_new)[t];
        ((t & 1) ? sA1 : sA0)[t >> 1] = hv;
    }
    __syncthreads();

    float p0 = 0.f, q0 = 0.f, p1 = 0.f, q1 = 0.f;
    #pragma unroll
    for (int c = 0; c < CH; c++) {
        CP_WAIT1();
        const int st = c % NSTG;
        const float4 a0 = sA0[c * 32 + lane], a1 = sA1[c * 32 + lane];
        const __half* tp = tileh + st * 512;
        uint4 w0 = *(const uint4*)(tp +       lane * 8);
        uint4 w1 = *(const uint4*)(tp + 256 + lane * 8);
        dot8(w0, a0, a1, p0, q0);
        dot8(w1, a0, a1, p1, q1);
        const int nc = c + NSTG - 1;
        if (nc < CH) {
            const uint32_t d = tileU + (nc % NSTG) * 1024;
            cp16(d,       rA0 + nc * CC + lane * 8);
            cp16(d + 512, rA0 + HDIM + nc * CC + lane * 8);
        }
        CP_COMMIT();
    }

    float v0 = p0 + q0, v1 = p1 + q1;
    #pragma unroll
    for (int o = 16; o > 0; o >>= 1) {
        v0 += __shfl_xor_sync(0xffffffffu, v0, o);
        v1 += __shfl_xor_sync(0xffffffffu, v1, o);
    }
    if (lane == 0) {
        s_g[2 * warp]     = v0 + pre1[rg0];
        s_g[2 * warp + 1] = v1 + pre1[rg0 + 1];
    }
    __syncthreads();
    if (t < 8) {
        const int u = blockIdx.x * 8 + t;
        float iv = sigmoidf_(s_g[t]);
        float fv = sigmoidf_(s_g[8 + t]);
        float gv = tanhf(s_g[16 + t]);
        float ov = sigmoidf_(s_g[24 + t]);
        float cn = fv * c1[u] + iv * gv;
        c1[u]     = cn;
        h1_out[u] = ov * tanhf(cn);
    }
}

// ===========================================================================
// K3 (R11 verbatim): logits + per-block exp-sum partials. 256 blocks.
// ===========================================================================
__global__ void __launch_bounds__(512, 2) step_k3(
    const __half* __restrict__ Wout,
    const float* __restrict__ bout,
    const float* __restrict__ h,
    float* __restrict__ logits,
    float* __restrict__ partials)
{
    extern __shared__ __align__(16) char smem[];
    float4* sA0 = (float4*)smem;
    float4* sA1 = sA0 + 256;
    __half* tiles = (__half*)(smem + 8192);
    __shared__ float s_part[16];
    __shared__ float s_e[8];

    const int t = threadIdx.x, warp = t >> 5, lane = t & 31;
    const uint32_t tileU = (uint32_t)__cvta_generic_to_shared(smem)
                           + 8192 + warp * 2048 + lane * 16;
    const __half* tileh = tiles + warp * 1024;

    const int row  = blockIdx.x * 8 + (warp >> 1);
    const int half = warp & 1;
    const __half* rA = Wout + (size_t)row * HDIM + half * 1024;

    #pragma unroll
    for (int c = 0; c < 4; c++) {
        cp16(tileU + c * 512, rA + c * CC + lane * 8);
        CP_COMMIT();
    }

    {
        float4 hv = ((const float4*)h)[t];
        ((t & 1) ? sA1 : sA0)[t >> 1] = hv;
    }
    __syncthreads();

    float p = 0.f, q = 0.f;
    const int ab = half * 128;
    asm volatile("cp.async.wait_group 3;" ::: "memory");
    {
        uint4 w = *(const uint4*)(tileh + lane * 8);
        dot8(w, sA0[ab + lane], sA1[ab + lane], p, q);
    }
    asm volatile("cp.async.wait_group 2;" ::: "memory");
    {
        uint4 w = *(const uint4*)(tileh + 256 + lane * 8);
        dot8(w, sA0[ab + 32 + lane], sA1[ab + 32 + lane], p, q);
    }
    asm volatile("cp.async.wait_group 1;" ::: "memory");
    {
        uint4 w = *(const uint4*)(tileh + 512 + lane * 8);
        dot8(w, sA0[ab + 64 + lane], sA1[ab + 64 + lane], p, q);
    }
    asm volatile("cp.async.wait_group 0;" ::: "memory");
    {
        uint4 w = *(const uint4*)(tileh + 768 + lane * 8);
        dot8(w, sA0[ab + 96 + lane], sA1[ab + 96 + lane], p, q);
    }

    float v = p + q;
    #pragma unroll
    for (int o = 16; o > 0; o >>= 1)
        v += __shfl_xor_sync(0xffffffffu, v, o);
    if (lane == 0) s_part[warp] = v;
    __syncthreads();
    if ((warp & 1) == 0 && lane == 0) {
        float lg = s_part[warp] + s_part[warp + 1] + bout[row];
        logits[row] = lg;
        s_e[warp >> 1] = __expf(lg);
    }
    __syncthreads();
    if (t == 0) {
        float se = 0.f;
        #pragma unroll
        for (int j = 0; j < 8; j++) se += s_e[j];
        partials[blockIdx.x] = se;
    }
}

// ===========================================================================
// One-shot fp32 -> fp16 conversion over all three weight arrays (R11).
// ===========================================================================
__global__ void __launch_bounds__(256) cvt_all(
    const float* __restrict__ a, __half* __restrict__ da, int na,
    const float* __restrict__ b, __half* __restrict__ db, int nb,
    const float* __restrict__ c, __half* __restrict__ dc, int ncnt)
{
    const int total = (na + nb + ncnt) >> 3;
    const int stride = gridDim.x * blockDim.x;
    for (int u = blockIdx.x * blockDim.x + threadIdx.x; u < total; u += stride) {
        const int i = u << 3;
        const float* s; __half* d;
        if (i < na)           { s = a + i;             d = da + i; }
        else if (i < na + nb) { s = b + (i - na);      d = db + (i - na); }
        else                  { s = c + (i - na - nb); d = dc + (i - na - nb); }
        float4 x0 = *(const float4*)s;
        float4 x1 = *(const float4*)(s + 4);
        __half2 h0 = __floats2half2_rn(x0.x, x0.y);
        __half2 h1 = __floats2half2_rn(x0.z, x0.w);
        __half2 h2 = __floats2half2_rn(x1.x, x1.y);
        __half2 h3 = __floats2half2_rn(x1.z, x1.w);
        uint4 o;
        o.x = *(unsigned*)&h0; o.y = *(unsigned*)&h1;
        o.z = *(unsigned*)&h2; o.w = *(unsigned*)&h3;
        *(uint4*)d = o;
    }
}

// Final step's softmax output row.
__global__ void __launch_bounds__(512) final_softmax_kernel(
    const float* __restrict__ logits,
    const float* __restrict__ partials,
    float* __restrict__ out_row)
{
    __shared__ float s_inv;
    const int t = threadIdx.x, warp = t >> 5, lane = t & 31;
    if (warp == 0) {
        float s = 0.0f;
        #pragma unroll
        for (int j = 0; j < 8; j++) s += partials[lane + j * 32];
        #pragma unroll
        for (int o = 16; o > 0; o >>= 1)
            s += __shfl_xor_sync(0xffffffffu, s, o);
        if (lane == 0) s_inv = 1.0f / s;
    }
    __syncthreads();
    const float inv = s_inv;
    float4 lg = ((const float4*)logits)[t];
    float4 v;
    v.x = __expf(lg.x) * inv;
    v.y = __expf(lg.y) * inv;
    v.z = __expf(lg.z) * inv;
    v.w = __expf(lg.w) * inv;
    ((float4*)out_row)[t] = v;
}

// ---------------------------------------------------------------------------
extern "C" void kernel_launch(void* const* d_in, const int* in_sizes, int n_in,
                              void* d_out, int out_size)
{
    const float* x    = (const float*)d_in[0];
    const float* Wih  = (const float*)d_in[1];
    const float* Whh  = (const float*)d_in[2];
    const float* bih  = (const float*)d_in[3];
    const float* bhh  = (const float*)d_in[4];
    const float* Wout = (const float*)d_in[5];
    const float* bout = (const float*)d_in[6];
    float* out = (float*)d_out;

    float *h0, *h1, *cbuf, *gl, *gp, *pre1;
    __half *wih16, *whh16, *wout16;
    cudaGetSymbolAddress((void**)&h0,     g_h0);
    cudaGetSymbolAddress((void**)&h1,     g_h1);
    cudaGetSymbolAddress((void**)&cbuf,   g_c);
    cudaGetSymbolAddress((void**)&gl,     g_logits);
    cudaGetSymbolAddress((void**)&gp,     g_partial);
    cudaGetSymbolAddress((void**)&pre1,   g_pre1);
    cudaGetSymbolAddress((void**)&wih16,  g_wih16);
    cudaGetSymbolAddress((void**)&whh16,  g_whh16);
    cudaGetSymbolAddress((void**)&wout16, g_wout16);

    const int SM_K1 = 16384 + 16 * 6144;   // 114688
    const int SM_K2 = 8192 + 16 * 3072;    // 57344
    const int SM_K3 = 8192 + 16 * 2048;    // 40960
    cudaFuncSetAttribute(step_k1<0>, cudaFuncAttributeMaxDynamicSharedMemorySize, SM_K1);
    cudaFuncSetAttribute(step_k1<1>, cudaFuncAttributeMaxDynamicSharedMemorySize, SM_K1);
    cudaFuncSetAttribute(step_k2,    cudaFuncAttributeMaxDynamicSharedMemorySize, SM_K2);
    cudaFuncSetAttribute(step_k3,    cudaFuncAttributeMaxDynamicSharedMemorySize, SM_K3);

    cudaMemsetAsync(h0, 0, sizeof(float) * HDIM);           // h0[0]
    cudaMemsetAsync(h1, 0, sizeof(float) * HDIM);           // h1[0]
    cudaMemsetAsync(cbuf, 0, sizeof(float) * 2 * HDIM);     // c0, c1

    const int NW = 2 * 4 * HDIM * HDIM;
    const int NO = SDIM * HDIM;
    cvt_all<<<2048, 256>>>(Wih, wih16, NW, Whh, whh16, NW, Wout, wout16, NO);

    const size_t wOffL = (size_t)4 * HDIM * HDIM;
    const size_t bOffL = (size_t)4 * HDIM;

    for (int s = 0; s < ANUM; s++) {
        const int r = s & 1;
        const int w = 1 - r;
        float* h0_in  = h0 + (size_t)r * HDIM;
        float* h0_out = h0 + (size_t)w * HDIM;
        float* h1_in  = h1 + (size_t)r * HDIM;
        float* h1_out = h1 + (size_t)w * HDIM;

        if (s == 0) {
            step_k1<1><<<NB1, 512, SM_K1>>>(
                wih16, whh16, whh16 + wOffL,
                bih, bhh, bih + bOffL, bhh + bOffL,
                x, nullptr, nullptr, nullptr,
                h0_in, h0_out, h1_in, cbuf, pre1);
        } else {
            step_k1<0><<<NB1, 512, SM_K1>>>(
                wih16, whh16, whh16 + wOffL,
                bih, bhh, bih + bOffL, bhh + bOffL,
                nullptr, gl, gp, out + (size_t)(s - 1) * SDIM,
                h0_in, h0_out, h1_in, cbuf, pre1);
        }
        step_k2<<<NB_2, 512, SM_K2>>>(
            wih16 + wOffL, pre1, h0_out, h1_out, cbuf + HDIM);
        step_k3<<<NB_3, 512, SM_K3>>>(
            wout16, bout, h1_out, gl, gp);
    }

    final_softmax_kernel<<<1, 512>>>(gl, gp, out + (size_t)(ANUM - 1) * SDIM);
}

// round 16
// speedup vs baseline: 1.1376x; 1.1376x over previous
#include <cuda_runtime.h>
#include <cuda_fp16.h>
#include <cstdint>
#include <math.h>

#define SDIM 2048
#define HDIM 2048
#define ANUM 16
#define NB_A 256      // K1a blocks (layer0 gates, 8 units each)
#define NB_3 256      // logits blocks (8 rows each, half-row per warp)
#define CH   8        // chunks per row (2048 / 256)
#define CC   256      // halfs per chunk per row per matrix
#define NSTG 3        // pipeline stages

// Persistent scratch
__device__ __align__(16) float g_h0[2][HDIM];
__device__ __align__(16) float g_h1[2][HDIM];
__device__ __align__(16) float g_c[2][HDIM];
__device__ __align__(16) float g_pre1[4 * HDIM];
__device__ __align__(16) float g_logits[SDIM];
__device__ __align__(16) float g_partial[NB_3];
__device__ __align__(16) __half g_wih16[2 * 4 * HDIM * HDIM];
__device__ __align__(16) __half g_whh16[2 * 4 * HDIM * HDIM];
__device__ __align__(16) __half g_wout16[SDIM * HDIM];

__device__ __forceinline__ float sigmoidf_(float x) {
    return 1.0f / (1.0f + __expf(-x));
}

__device__ __forceinline__ void cp16(uint32_t dst, const void* src) {
    asm volatile("cp.async.cg.shared.global [%0], [%1], 16;"
                 :: "r"(dst), "l"(src) : "memory");
}
#define CP_COMMIT() asm volatile("cp.async.commit_group;" ::: "memory")
#define CP_WAIT1()  asm volatile("cp.async.wait_group 1;"  ::: "memory")

// 8 half-weights (uint4) dot 8 floats (two float4), into two accumulators.
__device__ __forceinline__ void dot8(uint4 w, float4 lo, float4 hi,
                                     float& p, float& q) {
    const __half2* hp = reinterpret_cast<const __half2*>(&w);
    float2 f0 = __half22float2(hp[0]);
    float2 f1 = __half22float2(hp[1]);
    float2 f2 = __half22float2(hp[2]);
    float2 f3 = __half22float2(hp[3]);
    p = fmaf(f0.x, lo.x, p); q = fmaf(f0.y, lo.y, q);
    p = fmaf(f1.x, lo.z, p); q = fmaf(f1.y, lo.w, q);
    p = fmaf(f2.x, hi.x, p); q = fmaf(f2.y, hi.y, q);
    p = fmaf(f3.x, hi.z, p); q = fmaf(f3.y, hi.w, q);
}

// ===========================================================================
// K1a: layer-0 full gates only (R11 typeA verbatim). 256 blocks x 512 thr,
// 2 rows/warp, per-warp cp.async pipeline.
// ===========================================================================
template<int FIRST>
__global__ void __launch_bounds__(512, 2) step_k1a(
    const __half* __restrict__ Wih0, const __half* __restrict__ Whh0,
    const float* __restrict__ bih0, const float* __restrict__ bhh0,
    const float* __restrict__ xin,
    const float* __restrict__ logits, const float* __restrict__ partials,
    float* __restrict__ out_prev,
    const float* __restrict__ h0_in, float* __restrict__ h0_out,
    float* __restrict__ c0)
{
    extern __shared__ __align__(16) char smem[];
    float4* sIn0 = (float4*)smem;
    float4* sIn1 = sIn0 + 256;
    float4* sH0  = sIn1 + 256;
    float4* sH1  = sH0 + 256;
    __half* tiles = (__half*)(smem + 16384);
    __shared__ float s_g[32];
    __shared__ float s_inv;

    const int t = threadIdx.x, warp = t >> 5, lane = t & 31;
    const uint32_t smemU = (uint32_t)__cvta_generic_to_shared(smem);
    const uint32_t tileU = smemU + 16384 + warp * 6144 + lane * 16;
    const __half* tileh  = tiles + warp * 3072;

    const int i0 = 2 * warp;
    const int rg0 = (i0 >> 3) * HDIM + blockIdx.x * 8 + (i0 & 7);
    const __half* rA0 = Wih0 + (size_t)rg0 * HDIM;
    const __half* rB0 = Whh0 + (size_t)rg0 * HDIM;

    #pragma unroll
    for (int s = 0; s < NSTG - 1; s++) {
        const uint32_t d = tileU + s * 2048;
        cp16(d,        rA0 + s * CC + lane * 8);
        cp16(d + 512,  rA0 + HDIM + s * CC + lane * 8);
        cp16(d + 1024, rB0 + s * CC + lane * 8);
        cp16(d + 1536, rB0 + HDIM + s * CC + lane * 8);
        CP_COMMIT();
    }

    if (!FIRST) {
        if (warp == 0) {
            float s = 0.0f;
            #pragma unroll
            for (int j = 0; j < 8; j++) s += partials[lane + j * 32];
            #pragma unroll
            for (int o = 16; o > 0; o >>= 1)
                s += __shfl_xor_sync(0xffffffffu, s, o);
            if (lane == 0) s_inv = 1.0f / s;
        }
        __syncthreads();
    }
    {
        float4 v;
        if (FIRST) {
            v = ((const float4*)xin)[t];
        } else {
            float4 lg = ((const float4*)logits)[t];
            const float inv = s_inv;
            v.x = __expf(lg.x) * inv;
            v.y = __expf(lg.y) * inv;
            v.z = __expf(lg.z) * inv;
            v.w = __expf(lg.w) * inv;
            if (blockIdx.x == 0) ((float4*)out_prev)[t] = v;
        }
        ((t & 1) ? sIn1 : sIn0)[t >> 1] = v;
        float4 hv = ((const float4*)h0_in)[t];
        ((t & 1) ? sH1 : sH0)[t >> 1] = hv;
    }
    __syncthreads();

    float p0 = 0.f, q0 = 0.f, p1 = 0.f, q1 = 0.f;
    #pragma unroll
    for (int c = 0; c < CH; c++) {
        CP_WAIT1();
        const int st = c % NSTG;
        const float4 a0 = sIn0[c * 32 + lane], a1 = sIn1[c * 32 + lane];
        const float4 b0 = sH0[c * 32 + lane],  b1 = sH1[c * 32 + lane];
        const __half* tp = tileh + st * 1024;
        uint4 wA0 = *(const uint4*)(tp +       lane * 8);
        uint4 wA1 = *(const uint4*)(tp + 256 + lane * 8);
        uint4 wB0 = *(const uint4*)(tp + 512 + lane * 8);
        uint4 wB1 = *(const uint4*)(tp + 768 + lane * 8);
        dot8(wA0, a0, a1, p0, q0);
        dot8(wB0, b0, b1, p0, q0);
        dot8(wA1, a0, a1, p1, q1);
        dot8(wB1, b0, b1, p1, q1);
        const int nc = c + NSTG - 1;
        if (nc < CH) {
            const uint32_t d = tileU + (nc % NSTG) * 2048;
            cp16(d,        rA0 + nc * CC + lane * 8);
            cp16(d + 512,  rA0 + HDIM + nc * CC + lane * 8);
            cp16(d + 1024, rB0 + nc * CC + lane * 8);
            cp16(d + 1536, rB0 + HDIM + nc * CC + lane * 8);
        }
        CP_COMMIT();
    }

    float v0 = p0 + q0, v1 = p1 + q1;
    #pragma unroll
    for (int o = 16; o > 0; o >>= 1) {
        v0 += __shfl_xor_sync(0xffffffffu, v0, o);
        v1 += __shfl_xor_sync(0xffffffffu, v1, o);
    }
    if (lane == 0) {
        s_g[2 * warp]     = v0 + bih0[rg0] + bhh0[rg0];
        s_g[2 * warp + 1] = v1 + bih0[rg0 + 1] + bhh0[rg0 + 1];
    }
    __syncthreads();
    if (t < 8) {
        const int u = blockIdx.x * 8 + t;
        float iv = sigmoidf_(s_g[t]);
        float fv = sigmoidf_(s_g[8 + t]);
        float gv = tanhf(s_g[16 + t]);
        float ov = sigmoidf_(s_g[24 + t]);
        float cn = fv * c0[u] + iv * gv;
        c0[u]     = cn;
        h0_out[u] = ov * tanhf(cn);
    }
}

// ===========================================================================
// K2 (R11 verbatim): layer-1 input half + pointwise. 256 blocks, 2 rows/warp.
// ===========================================================================
__global__ void __launch_bounds__(512, 2) step_k2(
    const __half* __restrict__ Wih1,
    const float* __restrict__ pre1,
    const float* __restrict__ h0_new,
    float* __restrict__ h1_out, float* __restrict__ c1)
{
    extern __shared__ __align__(16) char smem[];
    float4* sA0 = (float4*)smem;
    float4* sA1 = sA0 + 256;
    __half* tiles = (__half*)(smem + 8192);
    __shared__ float s_g[32];

    const int t = threadIdx.x, warp = t >> 5, lane = t & 31;
    const uint32_t smemU = (uint32_t)__cvta_generic_to_shared(smem);
    const uint32_t tileU = smemU + 8192 + warp * 3072 + lane * 16;
    const __half* tileh  = tiles + warp * 1536;

    const int i0 = 2 * warp;
    const int rg0 = (i0 >> 3) * HDIM + blockIdx.x * 8 + (i0 & 7);
    const __half* rA0 = Wih1 + (size_t)rg0 * HDIM;

    #pragma unroll
    for (int s = 0; s < NSTG - 1; s++) {
        const uint32_t d = tileU + s * 1024;
        cp16(d,       rA0 + s * CC + lane * 8);
        cp16(d + 512, rA0 + HDIM + s * CC + lane * 8);
        CP_COMMIT();
    }

    {
        float4 hv = ((const float4*)h0_new)[t];
        ((t & 1) ? sA1 : sA0)[t >> 1] = hv;
    }
    __syncthreads();

    float p0 = 0.f, q0 = 0.f, p1 = 0.f, q1 = 0.f;
    #pragma unroll
    for (int c = 0; c < CH; c++) {
        CP_WAIT1();
        const int st = c % NSTG;
        const float4 a0 = sA0[c * 32 + lane], a1 = sA1[c * 32 + lane];
        const __half* tp = tileh + st * 512;
        uint4 w0 = *(const uint4*)(tp +       lane * 8);
        uint4 w1 = *(const uint4*)(tp + 256 + lane * 8);
        dot8(w0, a0, a1, p0, q0);
        dot8(w1, a0, a1, p1, q1);
        const int nc = c + NSTG - 1;
        if (nc < CH) {
            const uint32_t d = tileU + (nc % NSTG) * 1024;
            cp16(d,       rA0 + nc * CC + lane * 8);
            cp16(d + 512, rA0 + HDIM + nc * CC + lane * 8);
        }
        CP_COMMIT();
    }

    float v0 = p0 + q0, v1 = p1 + q1;
    #pragma unroll
    for (int o = 16; o > 0; o >>= 1) {
        v0 += __shfl_xor_sync(0xffffffffu, v0, o);
        v1 += __shfl_xor_sync(0xffffffffu, v1, o);
    }
    if (lane == 0) {
        s_g[2 * warp]     = v0 + pre1[rg0];
        s_g[2 * warp + 1] = v1 + pre1[rg0 + 1];
    }
    __syncthreads();
    if (t < 8) {
        const int u = blockIdx.x * 8 + t;
        float iv = sigmoidf_(s_g[t]);
        float fv = sigmoidf_(s_g[8 + t]);
        float gv = tanhf(s_g[16 + t]);
        float ov = sigmoidf_(s_g[24 + t]);
        float cn = fv * c1[u] + iv * gv;
        c1[u]     = cn;
        h1_out[u] = ov * tanhf(cn);
    }
}

// ===========================================================================
// K3b: 512 blocks. bids [0,256): R11 K3 logits body (reads h1_out).
// bids [256,512): R11 K1-typeB body -> pre1 for NEXT step (same h1_out).
// Dyn smem = max(40960, 57344) = 57344.
// ===========================================================================
__global__ void __launch_bounds__(512, 2) step_k3b(
    const __half* __restrict__ Wout,
    const float* __restrict__ bout,
    const __half* __restrict__ Whh1,
    const float* __restrict__ bih1, const float* __restrict__ bhh1,
    const float* __restrict__ h,
    float* __restrict__ logits,
    float* __restrict__ partials,
    float* __restrict__ pre1)
{
    extern __shared__ __align__(16) char smem[];
    float4* sA0 = (float4*)smem;
    float4* sA1 = sA0 + 256;
    __shared__ float s_part[16];
    __shared__ float s_e[8];

    const int t = threadIdx.x, warp = t >> 5, lane = t & 31;
    const uint32_t smemU = (uint32_t)__cvta_generic_to_shared(smem);

    if (blockIdx.x < NB_3) {
        // ---------------- logits body (R11 step_k3 verbatim) ----------------
        __half* tiles = (__half*)(smem + 8192);
        const uint32_t tileU = smemU + 8192 + warp * 2048 + lane * 16;
        const __half* tileh = tiles + warp * 1024;

        const int row  = blockIdx.x * 8 + (warp >> 1);
        const int half = warp & 1;
        const __half* rA = Wout + (size_t)row * HDIM + half * 1024;

        #pragma unroll
        for (int c = 0; c < 4; c++) {
            cp16(tileU + c * 512, rA + c * CC + lane * 8);
            CP_COMMIT();
        }
        {
            float4 hv = ((const float4*)h)[t];
            ((t & 1) ? sA1 : sA0)[t >> 1] = hv;
        }
        __syncthreads();

        float p = 0.f, q = 0.f;
        const int ab = half * 128;
        asm volatile("cp.async.wait_group 3;" ::: "memory");
        {
            uint4 w = *(const uint4*)(tileh + lane * 8);
            dot8(w, sA0[ab + lane], sA1[ab + lane], p, q);
        }
        asm volatile("cp.async.wait_group 2;" ::: "memory");
        {
            uint4 w = *(const uint4*)(tileh + 256 + lane * 8);
            dot8(w, sA0[ab + 32 + lane], sA1[ab + 32 + lane], p, q);
        }
        asm volatile("cp.async.wait_group 1;" ::: "memory");
        {
            uint4 w = *(const uint4*)(tileh + 512 + lane * 8);
            dot8(w, sA0[ab + 64 + lane], sA1[ab + 64 + lane], p, q);
        }
        asm volatile("cp.async.wait_group 0;" ::: "memory");
        {
            uint4 w = *(const uint4*)(tileh + 768 + lane * 8);
            dot8(w, sA0[ab + 96 + lane], sA1[ab + 96 + lane], p, q);
        }

        float v = p + q;
        #pragma unroll
        for (int o = 16; o > 0; o >>= 1)
            v += __shfl_xor_sync(0xffffffffu, v, o);
        if (lane == 0) s_part[warp] = v;
        __syncthreads();
        if ((warp & 1) == 0 && lane == 0) {
            float lg = s_part[warp] + s_part[warp + 1] + bout[row];
            logits[row] = lg;
            s_e[warp >> 1] = __expf(lg);
        }
        __syncthreads();
        if (t == 0) {
            float se = 0.f;
            #pragma unroll
            for (int j = 0; j < 8; j++) se += s_e[j];
            partials[blockIdx.x] = se;
        }
    } else {
        // ------------- typeB body (R11 K1 else-branch verbatim) -------------
        __half* tiles = (__half*)(smem + 8192);
        const uint32_t tileU = smemU + 8192 + warp * 3072 + lane * 16;
        const __half* tileh = tiles + warp * 1536;

        const int rg0 = (blockIdx.x - NB_3) * 32 + 2 * warp;
        const __half* rA0 = Whh1 + (size_t)rg0 * HDIM;

        #pragma unroll
        for (int s = 0; s < NSTG - 1; s++) {
            const uint32_t d = tileU + s * 1024;
            cp16(d,       rA0 + s * CC + lane * 8);
            cp16(d + 512, rA0 + HDIM + s * CC + lane * 8);
            CP_COMMIT();
        }
        {
            float4 hv = ((const float4*)h)[t];
            ((t & 1) ? sA1 : sA0)[t >> 1] = hv;
        }
        __syncthreads();

        float p0 = 0.f, q0 = 0.f, p1 = 0.f, q1 = 0.f;
        #pragma unroll
        for (int c = 0; c < CH; c++) {
            CP_WAIT1();
            const int st = c % NSTG;
            const float4 a0 = sA0[c * 32 + lane], a1 = sA1[c * 32 + lane];
            const __half* tp = tileh + st * 512;
            uint4 w0 = *(const uint4*)(tp +       lane * 8);
            uint4 w1 = *(const uint4*)(tp + 256 + lane * 8);
            dot8(w0, a0, a1, p0, q0);
            dot8(w1, a0, a1, p1, q1);
            const int nc = c + NSTG - 1;
            if (nc < CH) {
                const uint32_t d = tileU + (nc % NSTG) * 1024;
                cp16(d,       rA0 + nc * CC + lane * 8);
                cp16(d + 512, rA0 + HDIM + nc * CC + lane * 8);
            }
            CP_COMMIT();
        }

        float v0 = p0 + q0, v1 = p1 + q1;
        #pragma unroll
        for (int o = 16; o > 0; o >>= 1) {
            v0 += __shfl_xor_sync(0xffffffffu, v0, o);
            v1 += __shfl_xor_sync(0xffffffffu, v1, o);
        }
        if (lane == 0) {
            pre1[rg0]     = v0 + bih1[rg0] + bhh1[rg0];
            pre1[rg0 + 1] = v1 + bih1[rg0 + 1] + bhh1[rg0 + 1];
        }
    }
}

// K3 plain (R11 verbatim) for the last step (no pre1 needed afterwards).
__global__ void __launch_bounds__(512, 2) step_k3(
    const __half* __restrict__ Wout,
    const float* __restrict__ bout,
    const float* __restrict__ h,
    float* __restrict__ logits,
    float* __restrict__ partials)
{
    extern __shared__ __align__(16) char smem[];
    float4* sA0 = (float4*)smem;
    float4* sA1 = sA0 + 256;
    __half* tiles = (__half*)(smem + 8192);
    __shared__ float s_part[16];
    __shared__ float s_e[8];

    const int t = threadIdx.x, warp = t >> 5, lane = t & 31;
    const uint32_t tileU = (uint32_t)__cvta_generic_to_shared(smem)
                           + 8192 + warp * 2048 + lane * 16;
    const __half* tileh = tiles + warp * 1024;

    const int row  = blockIdx.x * 8 + (warp >> 1);
    const int half = warp & 1;
    const __half* rA = Wout + (size_t)row * HDIM + half * 1024;

    #pragma unroll
    for (int c = 0; c < 4; c++) {
        cp16(tileU + c * 512, rA + c * CC + lane * 8);
        CP_COMMIT();
    }
    {
        float4 hv = ((const float4*)h)[t];
        ((t & 1) ? sA1 : sA0)[t >> 1] = hv;
    }
    __syncthreads();

    float p = 0.f, q = 0.f;
    const int ab = half * 128;
    asm volatile("cp.async.wait_group 3;" ::: "memory");
    {
        uint4 w = *(const uint4*)(tileh + lane * 8);
        dot8(w, sA0[ab + lane], sA1[ab + lane], p, q);
    }
    asm volatile("cp.async.wait_group 2;" ::: "memory");
    {
        uint4 w = *(const uint4*)(tileh + 256 + lane * 8);
        dot8(w, sA0[ab + 32 + lane], sA1[ab + 32 + lane], p, q);
    }
    asm volatile("cp.async.wait_group 1;" ::: "memory");
    {
        uint4 w = *(const uint4*)(tileh + 512 + lane * 8);
        dot8(w, sA0[ab + 64 + lane], sA1[ab + 64 + lane], p, q);
    }
    asm volatile("cp.async.wait_group 0;" ::: "memory");
    {
        uint4 w = *(const uint4*)(tileh + 768 + lane * 8);
        dot8(w, sA0[ab + 96 + lane], sA1[ab + 96 + lane], p, q);
    }

    float v = p + q;
    #pragma unroll
    for (int o = 16; o > 0; o >>= 1)
        v += __shfl_xor_sync(0xffffffffu, v, o);
    if (lane == 0) s_part[warp] = v;
    __syncthreads();
    if ((warp & 1) == 0 && lane == 0) {
        float lg = s_part[warp] + s_part[warp + 1] + bout[row];
        logits[row] = lg;
        s_e[warp >> 1] = __expf(lg);
    }
    __syncthreads();
    if (t == 0) {
        float se = 0.f;
        #pragma unroll
        for (int j = 0; j < 8; j++) se += s_e[j];
        partials[blockIdx.x] = se;
    }
}

// pre1 init for step 0: h1 = 0 so pre1 = bih1 + bhh1. 16 blocks x 512.
__global__ void __launch_bounds__(512) pre1_init_kernel(
    float* __restrict__ pre1,
    const float* __restrict__ bih1, const float* __restrict__ bhh1)
{
    const int i = blockIdx.x * 512 + threadIdx.x;
    pre1[i] = bih1[i] + bhh1[i];
}

// ===========================================================================
// One-shot fp32 -> fp16 conversion over all three weight arrays (R11).
// ===========================================================================
__global__ void __launch_bounds__(256) cvt_all(
    const float* __restrict__ a, __half* __restrict__ da, int na,
    const float* __restrict__ b, __half* __restrict__ db, int nb,
    const float* __restrict__ c, __half* __restrict__ dc, int ncnt)
{
    const int total = (na + nb + ncnt) >> 3;
    const int stride = gridDim.x * blockDim.x;
    for (int u = blockIdx.x * blockDim.x + threadIdx.x; u < total; u += stride) {
        const int i = u << 3;
        const float* s; __half* d;
        if (i < na)           { s = a + i;             d = da + i; }
        else if (i < na + nb) { s = b + (i - na);      d = db + (i - na); }
        else                  { s = c + (i - na - nb); d = dc + (i - na - nb); }
        float4 x0 = *(const float4*)s;
        float4 x1 = *(const float4*)(s + 4);
        __half2 h0 = __floats2half2_rn(x0.x, x0.y);
        __half2 h1 = __floats2half2_rn(x0.z, x0.w);
        __half2 h2 = __floats2half2_rn(x1.x, x1.y);
        __half2 h3 = __floats2half2_rn(x1.z, x1.w);
        uint4 o;
        o.x = *(unsigned*)&h0; o.y = *(unsigned*)&h1;
        o.z = *(unsigned*)&h2; o.w = *(unsigned*)&h3;
        *(uint4*)d = o;
    }
}

// Final step's softmax output row.
__global__ void __launch_bounds__(512) final_softmax_kernel(
    const float* __restrict__ logits,
    const float* __restrict__ partials,
    float* __restrict__ out_row)
{
    __shared__ float s_inv;
    const int t = threadIdx.x, warp = t >> 5, lane = t & 31;
    if (warp == 0) {
        float s = 0.0f;
        #pragma unroll
        for (int j = 0; j < 8; j++) s += partials[lane + j * 32];
        #pragma unroll
        for (int o = 16; o > 0; o >>= 1)
            s += __shfl_xor_sync(0xffffffffu, s, o);
        if (lane == 0) s_inv = 1.0f / s;
    }
    __syncthreads();
    const float inv = s_inv;
    float4 lg = ((const float4*)logits)[t];
    float4 v;
    v.x = __expf(lg.x) * inv;
    v.y = __expf(lg.y) * inv;
    v.z = __expf(lg.z) * inv;
    v.w = __expf(lg.w) * inv;
    ((float4*)out_row)[t] = v;
}

// ---------------------------------------------------------------------------
extern "C" void kernel_launch(void* const* d_in, const int* in_sizes, int n_in,
                              void* d_out, int out_size)
{
    const float* x    = (const float*)d_in[0];
    const float* Wih  = (const float*)d_in[1];
    const float* Whh  = (const float*)d_in[2];
    const float* bih  = (const float*)d_in[3];
    const float* bhh  = (const float*)d_in[4];
    const float* Wout = (const float*)d_in[5];
    const float* bout = (const float*)d_in[6];
    float* out = (float*)d_out;

    float *h0, *h1, *cbuf, *gl, *gp, *pre1;
    __half *wih16, *whh16, *wout16;
    cudaGetSymbolAddress((void**)&h0,     g_h0);
    cudaGetSymbolAddress((void**)&h1,     g_h1);
    cudaGetSymbolAddress((void**)&cbuf,   g_c);
    cudaGetSymbolAddress((void**)&gl,     g_logits);
    cudaGetSymbolAddress((void**)&gp,     g_partial);
    cudaGetSymbolAddress((void**)&pre1,   g_pre1);
    cudaGetSymbolAddress((void**)&wih16,  g_wih16);
    cudaGetSymbolAddress((void**)&whh16,  g_whh16);
    cudaGetSymbolAddress((void**)&wout16, g_wout16);

    const int SM_K1 = 16384 + 16 * 6144;   // 114688
    const int SM_K2 = 8192 + 16 * 3072;    // 57344
    const int SM_K3 = 8192 + 16 * 2048;    // 40960
    const int SM_3B = 8192 + 16 * 3072;    // 57344 (max of both branches)
    cudaFuncSetAttribute(step_k1a<0>, cudaFuncAttributeMaxDynamicSharedMemorySize, SM_K1);
    cudaFuncSetAttribute(step_k1a<1>, cudaFuncAttributeMaxDynamicSharedMemorySize, SM_K1);
    cudaFuncSetAttribute(step_k2,     cudaFuncAttributeMaxDynamicSharedMemorySize, SM_K2);
    cudaFuncSetAttribute(step_k3,     cudaFuncAttributeMaxDynamicSharedMemorySize, SM_K3);
    cudaFuncSetAttribute(step_k3b,    cudaFuncAttributeMaxDynamicSharedMemorySize, SM_3B);

    cudaMemsetAsync(h0, 0, sizeof(float) * HDIM);           // h0[0]
    cudaMemsetAsync(h1, 0, sizeof(float) * HDIM);           // h1[0]
    cudaMemsetAsync(cbuf, 0, sizeof(float) * 2 * HDIM);     // c0, c1

    const int NW = 2 * 4 * HDIM * HDIM;
    const int NO = SDIM * HDIM;
    cvt_all<<<2048, 256>>>(Wih, wih16, NW, Whh, whh16, NW, Wout, wout16, NO);

    const size_t wOffL = (size_t)4 * HDIM * HDIM;
    const size_t bOffL = (size_t)4 * HDIM;

    // pre1 for step 0 (h1 = 0): just the biases.
    pre1_init_kernel<<<16, 512>>>(pre1, bih + bOffL, bhh + bOffL);

    for (int s = 0; s < ANUM; s++) {
        const int r = s & 1;
        const int w = 1 - r;
        float* h0_in  = h0 + (size_t)r * HDIM;
        float* h0_out = h0 + (size_t)w * HDIM;
        float* h1_out = h1 + (size_t)w * HDIM;

        if (s == 0) {
            step_k1a<1><<<NB_A, 512, SM_K1>>>(
                wih16, whh16, bih, bhh,
                x, nullptr, nullptr, nullptr,
                h0_in, h0_out, cbuf);
        } else {
            step_k1a<0><<<NB_A, 512, SM_K1>>>(
                wih16, whh16, bih, bhh,
                nullptr, gl, gp, out + (size_t)(s - 1) * SDIM,
                h0_in, h0_out, cbuf);
        }
        step_k2<<<NB_A, 512, SM_K2>>>(
            wih16 + wOffL, pre1, h0_out, h1_out, cbuf + HDIM);
        if (s < ANUM - 1) {
            // logits for this step + pre1 for the NEXT step (reads h1_out)
            step_k3b<<<2 * NB_3, 512, SM_3B>>>(
                wout16, bout, whh16 + wOffL, bih + bOffL, bhh + bOffL,
                h1_out, gl, gp, pre1);
        } else {
            step_k3<<<NB_3, 512, SM_K3>>>(
                wout16, bout, h1_out, gl, gp);
        }
    }

    final_softmax_kernel<<<1, 512>>>(gl, gp, out + (size_t)(ANUM - 1) * SDIM);
}